// round 11
// baseline (speedup 1.0000x reference)
#include <cuda_runtime.h>
#include <math.h>

#define HW    256
#define EPS   1e-9f
#define KPAD  44        // v-table k range [0,43]; live support caps at s=41
#define NSLOT 6         // slots per lane; group of 8 lanes holds 48 slots

// FTZ fp32 ops — reference is XLA-GPU-compiled (ftz=true); subnormal flushing
// during the scan erodes the count support and sets the KL-plateau onset.
__device__ __forceinline__ float fmul_ftz(float a, float b) {
    float c; asm("mul.ftz.f32 %0, %1, %2;" : "=f"(c) : "f"(a), "f"(b)); return c;
}
__device__ __forceinline__ float fadd_ftz(float a, float b) {
    float c; asm("add.ftz.f32 %0, %1, %2;" : "=f"(c) : "f"(a), "f"(b)); return c;
}
__device__ __forceinline__ float fsub_ftz(float a, float b) {
    float c; asm("sub.ftz.f32 %0, %1, %2;" : "=f"(c) : "f"(a), "f"(b)); return c;
}
__device__ __forceinline__ float fdiv_ftz(float a, float b) {
    float c; asm("div.rn.ftz.f32 %0, %1, %2;" : "=f"(c) : "f"(a), "f"(b)); return c;
}

// Precomputed by setup kernel (device globals: no allocation).
__device__ float g_T[HW * KPAD];   // T[i][k] = div.rn.ftz(min(k, 256-i), 256-i)
__device__ float g_cd0[48];        // normalized initial count distribution

// ---------------- setup: v-table + cd0 (one small block) ----------------
__global__ void spair_setup_kernel()
{
    const int tid = threadIdx.x;
    for (int e = tid; e < HW * KPAD; e += blockDim.x) {
        const int i = e / KPAD;
        const int k = e - i * KPAD;
        const int d = HW - i;
        g_T[e] = fdiv_ftz((float)(k < d ? k : d), (float)d);
    }
    if (tid < 32) {   // warp 0: cd0 with the exact R10 summation order
        const int lane = tid;
        const float  p_f    = 1.0f / (expf(2.0f) + 1.0f);
        const double base_d = (double)p_f;
        const double omp_d  = 1.0 - base_d;
        float c0 = (float)(omp_d * pow(base_d, (double)lane));
        float c1 = (float)(omp_d * pow(base_d, (double)(lane + 32)));
        if (fabsf(c0) < 1.17549435e-38f) c0 = 0.0f;   // FTZ of cd0
        if (fabsf(c1) < 1.17549435e-38f) c1 = 0.0f;
        float acc = fadd_ftz(c0, c1);
#pragma unroll
        for (int off = 16; off; off >>= 1)
            acc = fadd_ftz(acc, __shfl_xor_sync(0xffffffffu, acc, off));
        g_cd0[lane] = fdiv_ftz(c0, acc);
        if (lane + 32 < 48) g_cd0[lane + 32] = fdiv_ftz(c1, acc);
    }
}

// ---------------- main scan: one warp = one batch row ----------------
__global__ __launch_bounds__(32)
void spair_obj_kl_kernel(const float* __restrict__ z_pres,
                         const float* __restrict__ z_pres_prob,
                         float* __restrict__ out, int B)
{
    __shared__ float         s_pz[HW];   // p_z per step -> epilogue
    __shared__ short         s_csf[HW];  // count_so_far per step (pure fn of bits)
    __shared__ unsigned char s_one[HW];  // sample bit per step

    const int lane = threadIdx.x;
    const int b    = blockIdx.x;
    if (b >= B) return;

    const float* zp = z_pres      + (size_t)b * HW;
    const float* pp = z_pres_prob + (size_t)b * HW;
    float*       o  = out         + (size_t)b * HW;

    // ---- sample bits -> per-step csf / is_one tables (all off the chain) ----
    unsigned mybits = 0;
#pragma unroll
    for (int j = 0; j < 8; ++j)
        mybits |= (rintf(zp[32 * j + lane]) > 0.5f) ? (1u << j) : 0u;
    unsigned w[8];
#pragma unroll
    for (int j = 0; j < 8; ++j)
        w[j] = __ballot_sync(0xffffffffu, (mybits >> j) & 1u);
    int prior = 0;
#pragma unroll
    for (int j = 0; j < 8; ++j) {
        const int t = 32 * j + lane;
        s_csf[t] = (short)(prior + __popc(w[j] & ((1u << lane) - 1u)));
        s_one[t] = (unsigned char)((w[j] >> lane) & 1u);
        prior   += __popc(w[j]);
    }
    __syncwarp();

    // ---- per-lane state: group of 8 lanes holds all 48 slots (4x replicated)
    const int glane = lane & 7;
    const int sbase = glane * NSLOT;          // slots sbase .. sbase+5
    float c[NSLOT];
#pragma unroll
    for (int j = 0; j < NSLOT; ++j) c[j] = g_cd0[sbase + j];

    float v[NSLOT];
#pragma unroll
    for (int j = 0; j < NSLOT; ++j) {        // v for step 0 (csf = 0)
        int k = sbase + j; k = k > 43 ? 43 : k;
        v[j] = g_T[k];
    }

    int i = 0, i_end = HW;
#pragma unroll 1
    for (; i < HW; ++i) {
        const bool is_one = s_one[i];

        float pz[NSLOT], u[NSLOT];
#pragma unroll
        for (int j = 0; j < NSLOT; ++j) {
            pz[j] = fmul_ftz(c[j], v[j]);
            const float m = is_one ? v[j] : fsub_ftz(1.0f, v[j]);
            u[j] = fmul_ftz(c[j], m);
        }

        // prefetch next step's v (independent of the fp recurrence)
        float vn[NSLOT];
        if (i + 1 < HW) {
            const int cs = s_csf[i + 1];
#pragma unroll
            for (int j = 0; j < NSLOT; ++j) {
                int k = sbase + j - cs;
                k = k < 0 ? 0 : (k > 43 ? 43 : k);
                vn[j] = g_T[(i + 1) * KPAD + k];
            }
        } else {
#pragma unroll
            for (int j = 0; j < NSLOT; ++j) vn[j] = 0.0f;
        }

        // local depth-3 trees, then 3-level xor within the 8-lane group
        // (each group holds the full support -> every lane gets the full sum)
        float psum = fadd_ftz(fadd_ftz(fadd_ftz(pz[0], pz[1]),
                                       fadd_ftz(pz[2], pz[3])),
                              fadd_ftz(pz[4], pz[5]));
        float nsum = fadd_ftz(fadd_ftz(fadd_ftz(u[0], u[1]),
                                       fadd_ftz(u[2], u[3])),
                              fadd_ftz(u[4], u[5]));
#pragma unroll
        for (int off = 1; off <= 4; off <<= 1) {
            nsum = fadd_ftz(nsum, __shfl_xor_sync(0xffffffffu, nsum, off));
            psum = fadd_ftz(psum, __shfl_xor_sync(0xffffffffu, psum, off));
        }

        if (lane == 0) s_pz[i] = psum;        // KL deferred to epilogue

        if (nsum == 0.0f) { i_end = i + 1; break; }   // absorbing collapse

        const float norm = fmaxf(nsum, 1e-6f);        // clip(., 1e-6, None)
#pragma unroll
        for (int j = 0; j < NSLOT; ++j) c[j] = fdiv_ftz(u[j], norm);
#pragma unroll
        for (int j = 0; j < NSLOT; ++j) v[j] = vn[j];
    }

    __syncwarp();

    // ---- epilogue: KL for all 256 steps in parallel (p_z = 0 after death) ----
#pragma unroll
    for (int j = 0; j < 8; ++j) {
        const int   idx = 32 * j + lane;
        const float pzv = (idx < i_end) ? s_pz[idx] : 0.0f;
        const float pr  = pp[idx];
        o[idx] = pr * (logf(pr + EPS) - logf(pzv + EPS))
               + (1.0f - pr) * (logf(1.0f - pr + EPS)
                                - logf((1.0f - pzv) + EPS));
    }
}

extern "C" void kernel_launch(void* const* d_in, const int* in_sizes, int n_in,
                              void* d_out, int out_size)
{
    const float* z_pres      = (const float*)d_in[0];
    const float* z_pres_prob = (const float*)d_in[1];
    float*       out         = (float*)d_out;

    const int B = in_sizes[0] / HW;          // 1024
    spair_setup_kernel<<<1, 256>>>();
    spair_obj_kl_kernel<<<B, 32>>>(z_pres, z_pres_prob, out, B);
}

// round 12
// speedup vs baseline: 2.7535x; 2.7535x over previous
#include <cuda_runtime.h>
#include <math.h>

#define HW    256
#define EPS   1e-9f
#define WPB   4         // warps per block, one batch row per warp
#define KPAD  44        // v-table k range [0,43]; live support caps at s=41
#define NSLOT 6         // slots per lane; 8-lane group holds all 48 slots

// FTZ fp32 ops — reference is XLA-GPU-compiled (ftz=true); subnormal flushing
// during the scan erodes the count support and sets the KL-plateau onset.
__device__ __forceinline__ float fmul_ftz(float a, float b) {
    float c; asm("mul.ftz.f32 %0, %1, %2;" : "=f"(c) : "f"(a), "f"(b)); return c;
}
__device__ __forceinline__ float fadd_ftz(float a, float b) {
    float c; asm("add.ftz.f32 %0, %1, %2;" : "=f"(c) : "f"(a), "f"(b)); return c;
}
__device__ __forceinline__ float fsub_ftz(float a, float b) {
    float c; asm("sub.ftz.f32 %0, %1, %2;" : "=f"(c) : "f"(a), "f"(b)); return c;
}
__device__ __forceinline__ float fdiv_ftz(float a, float b) {
    float c; asm("div.rn.ftz.f32 %0, %1, %2;" : "=f"(c) : "f"(a), "f"(b)); return c;
}
__device__ __forceinline__ float ffma_ftz(float a, float b, float c) {
    float d; asm("fma.rn.ftz.f32 %0, %1, %2, %3;" : "=f"(d) : "f"(a), "f"(b), "f"(c)); return d;
}
__device__ __forceinline__ float frcp_approx(float a) {
    float c; asm("rcp.approx.ftz.f32 %0, %1;" : "=f"(c) : "f"(a)); return c;
}

// Precomputed by setup kernel (device globals: no allocation).
__device__ float g_T[HW * KPAD];   // T[i][k] = div.rn.ftz(min(k, 256-i), 256-i)
__device__ float g_cd0[48];        // normalized initial count distribution

// ---------------- setup: v-table + cd0 (one small block) ----------------
__global__ void spair_setup_kernel()
{
    const int tid = threadIdx.x;
    for (int e = tid; e < HW * KPAD; e += blockDim.x) {
        const int i = e / KPAD;
        const int k = e - i * KPAD;
        const int d = HW - i;
        g_T[e] = fdiv_ftz((float)(k < d ? k : d), (float)d);
    }
    if (tid < 32) {   // warp 0: cd0 with the exact R10/R11 summation order
        const int lane = tid;
        const float  p_f    = 1.0f / (expf(2.0f) + 1.0f);
        const double base_d = (double)p_f;
        const double omp_d  = 1.0 - base_d;
        float c0 = (float)(omp_d * pow(base_d, (double)lane));
        float c1 = (float)(omp_d * pow(base_d, (double)(lane + 32)));
        if (fabsf(c0) < 1.17549435e-38f) c0 = 0.0f;   // FTZ of cd0
        if (fabsf(c1) < 1.17549435e-38f) c1 = 0.0f;
        float acc = fadd_ftz(c0, c1);
#pragma unroll
        for (int off = 16; off; off >>= 1)
            acc = fadd_ftz(acc, __shfl_xor_sync(0xffffffffu, acc, off));
        g_cd0[lane] = fdiv_ftz(c0, acc);
        if (lane + 32 < 48) g_cd0[lane + 32] = fdiv_ftz(c1, acc);
    }
}

// ---------------- main scan: one warp = one batch row ----------------
__global__ __launch_bounds__(WPB * 32)
void spair_obj_kl_kernel(const float* __restrict__ z_pres,
                         const float* __restrict__ z_pres_prob,
                         float* __restrict__ out, int B)
{
    __shared__ float         s_pz[WPB][HW];   // p_z per step -> epilogue
    __shared__ short         s_csf[WPB][HW];  // count_so_far (pure fn of bits)
    __shared__ unsigned char s_one[WPB][HW];  // sample bit per step

    const int warp = threadIdx.x >> 5;
    const int lane = threadIdx.x & 31;
    const int b    = blockIdx.x * WPB + warp;
    if (b >= B) return;

    const float* zp = z_pres      + (size_t)b * HW;
    const float* pp = z_pres_prob + (size_t)b * HW;
    float*       o  = out         + (size_t)b * HW;

    // ---- sample bits -> per-step csf / is_one tables (all off the chain) ----
    unsigned mybits = 0;
#pragma unroll
    for (int j = 0; j < 8; ++j)
        mybits |= (rintf(zp[32 * j + lane]) > 0.5f) ? (1u << j) : 0u;
    unsigned w[8];
#pragma unroll
    for (int j = 0; j < 8; ++j)
        w[j] = __ballot_sync(0xffffffffu, (mybits >> j) & 1u);
    int prior = 0;
#pragma unroll
    for (int j = 0; j < 8; ++j) {
        const int t = 32 * j + lane;
        s_csf[warp][t] = (short)(prior + __popc(w[j] & ((1u << lane) - 1u)));
        s_one[warp][t] = (unsigned char)((w[j] >> lane) & 1u);
        prior         += __popc(w[j]);
    }
    __syncwarp();

    // ---- per-lane state: each 8-lane group holds all 48 slots (4x groups) ----
    const int glane = lane & 7;
    const int sbase = glane * NSLOT;          // slots sbase .. sbase+5
    float c[NSLOT];
#pragma unroll
    for (int j = 0; j < NSLOT; ++j) c[j] = g_cd0[sbase + j];

    float v[NSLOT];
#pragma unroll
    for (int j = 0; j < NSLOT; ++j) {         // v for step 0 (csf = 0)
        int k = sbase + j; k = k > 43 ? 43 : k;
        v[j] = g_T[k];
    }

    const float SC_UP = 1.8446744073709552e19f;   // 2^64  (exact scaling)
    const float SC_DN = 5.421010862427522e-20f;   // 2^-64 (exact / FTZ-flush)

    int i = 0, i_end = HW;
#pragma unroll 1
    for (; i < HW; ++i) {
        const bool is_one = s_one[warp][i];

        float pz[NSLOT], u[NSLOT];
#pragma unroll
        for (int j = 0; j < NSLOT; ++j) {
            pz[j] = fmul_ftz(c[j], v[j]);
            const float m = is_one ? v[j] : fsub_ftz(1.0f, v[j]);
            u[j] = fmul_ftz(c[j], m);
        }

        // prefetch next step's v (independent of the fp recurrence)
        float vn[NSLOT];
        if (i + 1 < HW) {
            const int cs = s_csf[warp][i + 1];
#pragma unroll
            for (int j = 0; j < NSLOT; ++j) {
                int k = sbase + j - cs;
                k = k < 0 ? 0 : (k > 43 ? 43 : k);
                vn[j] = g_T[(i + 1) * KPAD + k];
            }
        } else {
#pragma unroll
            for (int j = 0; j < NSLOT; ++j) vn[j] = 0.0f;
        }

        // local depth-3 trees, then 3 xor levels within the 8-lane group
        // (same summation structure as the verified 9.786814e-09 trajectory)
        float psum = fadd_ftz(fadd_ftz(fadd_ftz(pz[0], pz[1]),
                                       fadd_ftz(pz[2], pz[3])),
                              fadd_ftz(pz[4], pz[5]));
        float nsum = fadd_ftz(fadd_ftz(fadd_ftz(u[0], u[1]),
                                       fadd_ftz(u[2], u[3])),
                              fadd_ftz(u[4], u[5]));
#pragma unroll
        for (int off = 1; off <= 4; off <<= 1) {
            nsum = fadd_ftz(nsum, __shfl_xor_sync(0xffffffffu, nsum, off));
            psum = fadd_ftz(psum, __shfl_xor_sync(0xffffffffu, psum, off));
        }

        if (lane == 0) s_pz[warp][i] = psum;   // KL deferred to epilogue

        if (nsum == 0.0f) { i_end = i + 1; break; }   // absorbing collapse

        // ---- branch-free correctly-rounded division c[j] = u[j]/norm ----
        // Markstein sequence on 2^64-scaled numerator: all intermediates
        // normal-range, final 2^-64 mul exact (or FTZ-flush, matching
        // div.rn.ftz's subnormal flush). Bit-identical to div.rn.ftz here.
        const float norm = fmaxf(nsum, 1e-6f);        // clip(., 1e-6, None)
        float y = frcp_approx(norm);
        const float e = ffma_ftz(-norm, y, 1.0f);
        y = ffma_ftz(e, y, y);                        // refined reciprocal
#pragma unroll
        for (int j = 0; j < NSLOT; ++j) {
            const float a  = fmul_ftz(u[j], SC_UP);   // exact 2^64 scale
            const float q0 = fmul_ftz(a, y);
            const float r  = ffma_ftz(-norm, q0, a);
            const float q1 = ffma_ftz(r, y, q0);      // correctly rounded
            c[j] = fmul_ftz(q1, SC_DN);               // exact unscale / flush
        }
#pragma unroll
        for (int j = 0; j < NSLOT; ++j) v[j] = vn[j];
    }

    __syncwarp();

    // ---- epilogue: KL for all 256 steps in parallel (p_z = 0 after death) ----
#pragma unroll
    for (int j = 0; j < 8; ++j) {
        const int   idx = 32 * j + lane;
        const float pzv = (idx < i_end) ? s_pz[warp][idx] : 0.0f;
        const float pr  = pp[idx];
        o[idx] = pr * (logf(pr + EPS) - logf(pzv + EPS))
               + (1.0f - pr) * (logf(1.0f - pr + EPS)
                                - logf((1.0f - pzv) + EPS));
    }
}

extern "C" void kernel_launch(void* const* d_in, const int* in_sizes, int n_in,
                              void* d_out, int out_size)
{
    const float* z_pres      = (const float*)d_in[0];
    const float* z_pres_prob = (const float*)d_in[1];
    float*       out         = (float*)d_out;

    const int B = in_sizes[0] / HW;              // 1024
    spair_setup_kernel<<<1, 256>>>();
    spair_obj_kl_kernel<<<(B + WPB - 1) / WPB, WPB * 32>>>(z_pres, z_pres_prob, out, B);
}

// round 13
// speedup vs baseline: 2.9393x; 1.0675x over previous
#include <cuda_runtime.h>
#include <math.h>

#define HW    256
#define EPS   1e-9f
#define WPB   4         // warps per block, one batch row per warp
#define KP    42        // v-table k range [0,41]; support caps at s=41
#define NSLOT 6         // slots per lane; 8-lane group holds all 48 slots

// FTZ fp32 ops — reference is XLA-GPU-compiled (ftz=true).
__device__ __forceinline__ float fmul_ftz(float a, float b) {
    float c; asm("mul.ftz.f32 %0, %1, %2;" : "=f"(c) : "f"(a), "f"(b)); return c;
}
__device__ __forceinline__ float fadd_ftz(float a, float b) {
    float c; asm("add.ftz.f32 %0, %1, %2;" : "=f"(c) : "f"(a), "f"(b)); return c;
}
__device__ __forceinline__ float fsub_ftz(float a, float b) {
    float c; asm("sub.ftz.f32 %0, %1, %2;" : "=f"(c) : "f"(a), "f"(b)); return c;
}
__device__ __forceinline__ float fdiv_ftz(float a, float b) {
    float c; asm("div.rn.ftz.f32 %0, %1, %2;" : "=f"(c) : "f"(a), "f"(b)); return c;
}
__device__ __forceinline__ float ffma_ftz(float a, float b, float c) {
    float d; asm("fma.rn.ftz.f32 %0, %1, %2, %3;" : "=f"(d) : "f"(a), "f"(b), "f"(c)); return d;
}
__device__ __forceinline__ float frcp_approx(float a) {
    float c; asm("rcp.approx.ftz.f32 %0, %1;" : "=f"(c) : "f"(a)); return c;
}
__device__ __forceinline__ int clampk(int k) {
    return k < 0 ? 0 : (k > KP - 1 ? KP - 1 : k);
}

// One scan step; bit-identical op structure to the verified R12 kernel.
// Returns nsum. Updates c[] in place, stores p_z.
__device__ __forceinline__ float scan_step(float* __restrict__ c,
                                           const float* __restrict__ v,
                                           bool is_one, int lane,
                                           float* __restrict__ pz_slot)
{
    const float SC_UP = 1.8446744073709552e19f;   // 2^64
    const float SC_DN = 5.421010862427522e-20f;   // 2^-64

    float pz[NSLOT], u[NSLOT];
#pragma unroll
    for (int j = 0; j < NSLOT; ++j) {
        pz[j] = fmul_ftz(c[j], v[j]);
        const float m = is_one ? v[j] : fsub_ftz(1.0f, v[j]);
        u[j] = fmul_ftz(c[j], m);
    }
    float psum = fadd_ftz(fadd_ftz(fadd_ftz(pz[0], pz[1]),
                                   fadd_ftz(pz[2], pz[3])),
                          fadd_ftz(pz[4], pz[5]));
    float nsum = fadd_ftz(fadd_ftz(fadd_ftz(u[0], u[1]),
                                   fadd_ftz(u[2], u[3])),
                          fadd_ftz(u[4], u[5]));
#pragma unroll
    for (int off = 1; off <= 4; off <<= 1) {
        nsum = fadd_ftz(nsum, __shfl_xor_sync(0xffffffffu, nsum, off));
        psum = fadd_ftz(psum, __shfl_xor_sync(0xffffffffu, psum, off));
    }
    if (lane == 0) *pz_slot = psum;

    const float norm = fmaxf(nsum, 1e-6f);
    float y = frcp_approx(norm);
    y = ffma_ftz(ffma_ftz(-norm, y, 1.0f), y, y);
#pragma unroll
    for (int j = 0; j < NSLOT; ++j) {
        const float a  = fmul_ftz(u[j], SC_UP);
        const float q0 = fmul_ftz(a, y);
        const float r  = ffma_ftz(-norm, q0, a);
        c[j] = fmul_ftz(ffma_ftz(r, y, q0), SC_DN);
    }
    return nsum;
}

__global__ __launch_bounds__(WPB * 32)
void spair_obj_kl_kernel(const float* __restrict__ z_pres,
                         const float* __restrict__ z_pres_prob,
                         float* __restrict__ out, int B)
{
    __shared__ float    s_T[HW * KP];     // v-table, 43 KB
    __shared__ float    s_pz[WPB][HW];
    __shared__ unsigned s_w[WPB][8];      // sample bits, 32 steps per word
    __shared__ float    s_cd0[48];

    const int tid  = threadIdx.x;
    const int warp = tid >> 5;
    const int lane = tid & 31;
    const int b    = blockIdx.x * WPB + warp;

    // ---- v-table: T[i][k] = div.rn.ftz(min(k, 256-i), 256-i). Unscaled
    // Markstein is correctly rounded here (integer operands, normal results,
    // r >= 2^-24) == bit-identical to div.rn.ftz.
    for (int e = tid; e < HW * KP; e += WPB * 32) {
        const int i = e / KP, k = e - i * KP, d = HW - i;
        const float fk = (float)(k < d ? k : d), fd = (float)d;
        float y = frcp_approx(fd);
        y = ffma_ftz(ffma_ftz(-fd, y, 1.0f), y, y);
        const float q0 = fmul_ftz(fk, y);
        const float r  = ffma_ftz(-fd, q0, fk);
        s_T[e] = ffma_ftz(r, y, q0);
    }

    // ---- cd0 (warp 0; exact setup-kernel ops from R12) ----
    if (warp == 0) {
        const float  p_f    = 1.0f / (expf(2.0f) + 1.0f);
        const double base_d = (double)p_f;
        const double omp_d  = 1.0 - base_d;
        float c0 = (float)(omp_d * pow(base_d, (double)lane));
        float c1 = (float)(omp_d * pow(base_d, (double)(lane + 32)));
        if (fabsf(c0) < 1.17549435e-38f) c0 = 0.0f;
        if (fabsf(c1) < 1.17549435e-38f) c1 = 0.0f;
        float acc = fadd_ftz(c0, c1);
#pragma unroll
        for (int off = 16; off; off >>= 1)
            acc = fadd_ftz(acc, __shfl_xor_sync(0xffffffffu, acc, off));
        s_cd0[lane] = fdiv_ftz(c0, acc);
        if (lane + 32 < 48) s_cd0[lane + 32] = fdiv_ftz(c1, acc);
    }

    // ---- sample bits (ballot words; uniform across warp -> lane 0 stores) --
    if (b < B) {
        const float* zp = z_pres + (size_t)b * HW;
        unsigned mybits = 0;
#pragma unroll
        for (int j = 0; j < 8; ++j)
            mybits |= (rintf(zp[32 * j + lane]) > 0.5f) ? (1u << j) : 0u;
#pragma unroll
        for (int j = 0; j < 8; ++j) {
            const unsigned wj = __ballot_sync(0xffffffffu, (mybits >> j) & 1u);
            if (lane == 0) s_w[warp][j] = wj;
        }
    }
    __syncthreads();
    if (b >= B) return;

    const float* pp = z_pres_prob + (size_t)b * HW;
    float*       o  = out         + (size_t)b * HW;

    const int sbase = (lane & 7) * NSLOT;     // 8-lane group owns all 48 slots
    float c[NSLOT];
#pragma unroll
    for (int j = 0; j < NSLOT; ++j) c[j] = s_cd0[sbase + j];

    float v0[NSLOT];                          // step-0 v (csf = 0)
#pragma unroll
    for (int j = 0; j < NSLOT; ++j) v0[j] = s_T[clampk(sbase + j)];

    int csf = 0, i_end = HW;
    unsigned cw = 0;

#pragma unroll 1
    for (int q = 0; q < HW / 4; ++q) {
        const int i0 = 4 * q;
        if ((q & 7) == 0) cw = s_w[warp][q >> 3];
        const int one0 = cw & 1, one1 = (cw >> 1) & 1,
                  one2 = (cw >> 2) & 1, one3 = (cw >> 3) & 1;
        const int csf1 = csf + one0, csf2 = csf1 + one1, csf3 = csf2 + one2;
        const int csfN = csf3 + one3;
        cw >>= 4;

        // prefetch v for steps 1..3 and next quartet's step 0 (all off-chain)
        float v1[NSLOT], v2[NSLOT], v3[NSLOT], vN[NSLOT];
        const int rN = (i0 + 4 < HW) ? (i0 + 4) : (HW - 1);
#pragma unroll
        for (int j = 0; j < NSLOT; ++j) {
            v1[j] = s_T[(i0 + 1) * KP + clampk(sbase + j - csf1)];
            v2[j] = s_T[(i0 + 2) * KP + clampk(sbase + j - csf2)];
            v3[j] = s_T[(i0 + 3) * KP + clampk(sbase + j - csf3)];
            vN[j] = s_T[rN * KP       + clampk(sbase + j - csfN)];
        }

        // four chained steps, no intervening control flow
        scan_step(c, v0, one0 != 0, lane, &s_pz[warp][i0 + 0]);
        scan_step(c, v1, one1 != 0, lane, &s_pz[warp][i0 + 1]);
        scan_step(c, v2, one2 != 0, lane, &s_pz[warp][i0 + 2]);
        const float ns = scan_step(c, v3, one3 != 0, lane, &s_pz[warp][i0 + 3]);

        csf = csfN;
#pragma unroll
        for (int j = 0; j < NSLOT; ++j) v0[j] = vN[j];

        // death is absorbing and zeros self-propagate within the quartet,
        // so checking only the 4th nsum is exact.
        if (ns == 0.0f) { i_end = i0 + 4; break; }
    }

    __syncwarp();

    // ---- epilogue: KL for all 256 steps in parallel (p_z = 0 after death) --
#pragma unroll
    for (int j = 0; j < 8; ++j) {
        const int   idx = 32 * j + lane;
        const float pzv = (idx < i_end) ? s_pz[warp][idx] : 0.0f;
        const float pr  = pp[idx];
        o[idx] = pr * (logf(pr + EPS) - logf(pzv + EPS))
               + (1.0f - pr) * (logf(1.0f - pr + EPS)
                                - logf((1.0f - pzv) + EPS));
    }
}

extern "C" void kernel_launch(void* const* d_in, const int* in_sizes, int n_in,
                              void* d_out, int out_size)
{
    const float* z_pres      = (const float*)d_in[0];
    const float* z_pres_prob = (const float*)d_in[1];
    float*       out         = (float*)d_out;

    const int B = in_sizes[0] / HW;          // 1024
    spair_obj_kl_kernel<<<(B + WPB - 1) / WPB, WPB * 32>>>(z_pres, z_pres_prob, out, B);
}

// round 14
// speedup vs baseline: 4.5644x; 1.5529x over previous
#include <cuda_runtime.h>
#include <math.h>

#define HW    256
#define EPS   1e-9f
#define WPB   8         // warps per block -> grid 128 <= 148 SMs: SINGLE WAVE
#define KP    42        // v-table k range [0,41]; support caps at s=41
#define NSLOT 6         // slots per lane; 8-lane group holds all 48 slots

// FTZ fp32 ops — reference is XLA-GPU-compiled (ftz=true).
__device__ __forceinline__ float fmul_ftz(float a, float b) {
    float c; asm("mul.ftz.f32 %0, %1, %2;" : "=f"(c) : "f"(a), "f"(b)); return c;
}
__device__ __forceinline__ float fadd_ftz(float a, float b) {
    float c; asm("add.ftz.f32 %0, %1, %2;" : "=f"(c) : "f"(a), "f"(b)); return c;
}
__device__ __forceinline__ float fsub_ftz(float a, float b) {
    float c; asm("sub.ftz.f32 %0, %1, %2;" : "=f"(c) : "f"(a), "f"(b)); return c;
}
__device__ __forceinline__ float fdiv_ftz(float a, float b) {
    float c; asm("div.rn.ftz.f32 %0, %1, %2;" : "=f"(c) : "f"(a), "f"(b)); return c;
}
__device__ __forceinline__ float ffma_ftz(float a, float b, float c) {
    float d; asm("fma.rn.ftz.f32 %0, %1, %2, %3;" : "=f"(d) : "f"(a), "f"(b), "f"(c)); return d;
}
__device__ __forceinline__ float frcp_approx(float a) {
    float c; asm("rcp.approx.ftz.f32 %0, %1;" : "=f"(c) : "f"(a)); return c;
}
__device__ __forceinline__ int clampk(int k) {
    return k < 0 ? 0 : (k > KP - 1 ? KP - 1 : k);
}

// One scan step; identical op structure / bits to the verified R12/R13 kernel.
// When is_one: u[j] is the same fmul(c[j], v[j]) as pz[j], so psum == nsum
// bitwise and the pz reduction is skipped (warp-uniform branch, no bit change).
__device__ __forceinline__ float scan_step(float* __restrict__ c,
                                           const float* __restrict__ v,
                                           bool is_one, int lane,
                                           float* __restrict__ pz_slot)
{
    const float SC_UP = 1.8446744073709552e19f;   // 2^64
    const float SC_DN = 5.421010862427522e-20f;   // 2^-64

    float u[NSLOT];
    float psum, nsum;

    if (is_one) {
#pragma unroll
        for (int j = 0; j < NSLOT; ++j)
            u[j] = fmul_ftz(c[j], v[j]);          // == pz[j] bitwise
        nsum = fadd_ftz(fadd_ftz(fadd_ftz(u[0], u[1]),
                                 fadd_ftz(u[2], u[3])),
                        fadd_ftz(u[4], u[5]));
#pragma unroll
        for (int off = 1; off <= 4; off <<= 1)
            nsum = fadd_ftz(nsum, __shfl_xor_sync(0xffffffffu, nsum, off));
        psum = nsum;                              // identical summands
    } else {
        float pz[NSLOT];
#pragma unroll
        for (int j = 0; j < NSLOT; ++j) {
            pz[j] = fmul_ftz(c[j], v[j]);
            u[j]  = fmul_ftz(c[j], fsub_ftz(1.0f, v[j]));
        }
        psum = fadd_ftz(fadd_ftz(fadd_ftz(pz[0], pz[1]),
                                 fadd_ftz(pz[2], pz[3])),
                        fadd_ftz(pz[4], pz[5]));
        nsum = fadd_ftz(fadd_ftz(fadd_ftz(u[0], u[1]),
                                 fadd_ftz(u[2], u[3])),
                        fadd_ftz(u[4], u[5]));
#pragma unroll
        for (int off = 1; off <= 4; off <<= 1) {
            nsum = fadd_ftz(nsum, __shfl_xor_sync(0xffffffffu, nsum, off));
            psum = fadd_ftz(psum, __shfl_xor_sync(0xffffffffu, psum, off));
        }
    }
    if (lane == 0) *pz_slot = psum;

    // branch-free correctly-rounded division (bit-identical to div.rn.ftz
    // on this kernel's domain; verified by the 9.786814e-09 canary)
    const float norm = fmaxf(nsum, 1e-6f);
    float y = frcp_approx(norm);
    y = ffma_ftz(ffma_ftz(-norm, y, 1.0f), y, y);
#pragma unroll
    for (int j = 0; j < NSLOT; ++j) {
        const float a  = fmul_ftz(u[j], SC_UP);
        const float q0 = fmul_ftz(a, y);
        const float r  = ffma_ftz(-norm, q0, a);
        c[j] = fmul_ftz(ffma_ftz(r, y, q0), SC_DN);
    }
    return nsum;
}

extern __shared__ float smem_dyn[];

__global__ __launch_bounds__(WPB * 32)
void spair_obj_kl_kernel(const float* __restrict__ z_pres,
                         const float* __restrict__ z_pres_prob,
                         float* __restrict__ out, int B)
{
    // dynamic smem carve: T[HW*KP] | pz[WPB*HW] | cd0[48] | bits[WPB*8]
    float*    s_T   = smem_dyn;
    float*    s_pz  = s_T + HW * KP;
    float*    s_cd0 = s_pz + WPB * HW;
    unsigned* s_w   = (unsigned*)(s_cd0 + 48);

    const int tid  = threadIdx.x;
    const int warp = tid >> 5;
    const int lane = tid & 31;
    const int b    = blockIdx.x * WPB + warp;

    // ---- v-table: T[i][k] = div.rn.ftz(min(k, 256-i), 256-i) via unscaled
    // Markstein (correctly rounded here: integer operands, normal results).
    for (int e = tid; e < HW * KP; e += WPB * 32) {
        const int i = e / KP, k = e - i * KP, d = HW - i;
        const float fk = (float)(k < d ? k : d), fd = (float)d;
        float y = frcp_approx(fd);
        y = ffma_ftz(ffma_ftz(-fd, y, 1.0f), y, y);
        const float q0 = fmul_ftz(fk, y);
        const float r  = ffma_ftz(-fd, q0, fk);
        s_T[e] = ffma_ftz(r, y, q0);
    }

    // ---- cd0 (warp 0; exact op order of the verified kernels) ----
    if (warp == 0) {
        const float  p_f    = 1.0f / (expf(2.0f) + 1.0f);
        const double base_d = (double)p_f;
        const double omp_d  = 1.0 - base_d;
        float c0 = (float)(omp_d * pow(base_d, (double)lane));
        float c1 = (float)(omp_d * pow(base_d, (double)(lane + 32)));
        if (fabsf(c0) < 1.17549435e-38f) c0 = 0.0f;
        if (fabsf(c1) < 1.17549435e-38f) c1 = 0.0f;
        float acc = fadd_ftz(c0, c1);
#pragma unroll
        for (int off = 16; off; off >>= 1)
            acc = fadd_ftz(acc, __shfl_xor_sync(0xffffffffu, acc, off));
        s_cd0[lane] = fdiv_ftz(c0, acc);
        if (lane + 32 < 48) s_cd0[lane + 32] = fdiv_ftz(c1, acc);
    }

    // ---- sample bits ----
    if (b < B) {
        const float* zp = z_pres + (size_t)b * HW;
        unsigned mybits = 0;
#pragma unroll
        for (int j = 0; j < 8; ++j)
            mybits |= (rintf(zp[32 * j + lane]) > 0.5f) ? (1u << j) : 0u;
#pragma unroll
        for (int j = 0; j < 8; ++j) {
            const unsigned wj = __ballot_sync(0xffffffffu, (mybits >> j) & 1u);
            if (lane == 0) s_w[warp * 8 + j] = wj;
        }
    }
    __syncthreads();
    if (b >= B) return;

    const float* pp  = z_pres_prob + (size_t)b * HW;
    float*       o   = out         + (size_t)b * HW;
    float*       pzb = s_pz + warp * HW;

    const int sbase = (lane & 7) * NSLOT;     // 8-lane group owns all 48 slots
    float c[NSLOT];
#pragma unroll
    for (int j = 0; j < NSLOT; ++j) c[j] = s_cd0[sbase + j];

    float v0[NSLOT];                          // step-0 v (csf = 0)
#pragma unroll
    for (int j = 0; j < NSLOT; ++j) v0[j] = s_T[clampk(sbase + j)];

    int csf = 0, i_end = HW;
    unsigned cw = 0;

#pragma unroll 1
    for (int q = 0; q < HW / 4; ++q) {
        const int i0 = 4 * q;
        if ((q & 7) == 0) cw = s_w[warp * 8 + (q >> 3)];
        const int one0 = cw & 1, one1 = (cw >> 1) & 1,
                  one2 = (cw >> 2) & 1, one3 = (cw >> 3) & 1;
        const int csf1 = csf + one0, csf2 = csf1 + one1, csf3 = csf2 + one2;
        const int csfN = csf3 + one3;
        cw >>= 4;

        // prefetch v for steps 1..3 and next quartet's step 0 (off-chain)
        float v1[NSLOT], v2[NSLOT], v3[NSLOT], vN[NSLOT];
        const int rN = (i0 + 4 < HW) ? (i0 + 4) : (HW - 1);
#pragma unroll
        for (int j = 0; j < NSLOT; ++j) {
            v1[j] = s_T[(i0 + 1) * KP + clampk(sbase + j - csf1)];
            v2[j] = s_T[(i0 + 2) * KP + clampk(sbase + j - csf2)];
            v3[j] = s_T[(i0 + 3) * KP + clampk(sbase + j - csf3)];
            vN[j] = s_T[rN * KP       + clampk(sbase + j - csfN)];
        }

        // four chained steps, no intervening control flow
        scan_step(c, v0, one0 != 0, lane, pzb + i0 + 0);
        scan_step(c, v1, one1 != 0, lane, pzb + i0 + 1);
        scan_step(c, v2, one2 != 0, lane, pzb + i0 + 2);
        const float ns = scan_step(c, v3, one3 != 0, lane, pzb + i0 + 3);

        csf = csfN;
#pragma unroll
        for (int j = 0; j < NSLOT; ++j) v0[j] = vN[j];

        // death is absorbing; zeros self-propagate within the quartet,
        // so checking only the 4th nsum is exact.
        if (ns == 0.0f) { i_end = i0 + 4; break; }
    }

    __syncwarp();

    // ---- epilogue: KL for all 256 steps in parallel (p_z = 0 after death) --
#pragma unroll
    for (int j = 0; j < 8; ++j) {
        const int   idx = 32 * j + lane;
        const float pzv = (idx < i_end) ? pzb[idx] : 0.0f;
        const float pr  = pp[idx];
        o[idx] = pr * (logf(pr + EPS) - logf(pzv + EPS))
               + (1.0f - pr) * (logf(1.0f - pr + EPS)
                                - logf((1.0f - pzv) + EPS));
    }
}

extern "C" void kernel_launch(void* const* d_in, const int* in_sizes, int n_in,
                              void* d_out, int out_size)
{
    const float* z_pres      = (const float*)d_in[0];
    const float* z_pres_prob = (const float*)d_in[1];
    float*       out         = (float*)d_out;

    const int B = in_sizes[0] / HW;              // 1024
    const int smem_bytes = (HW * KP + WPB * HW + 48 + WPB * 8) * 4;  // ~51.6 KB
    cudaFuncSetAttribute(spair_obj_kl_kernel,
                         cudaFuncAttributeMaxDynamicSharedMemorySize, smem_bytes);
    spair_obj_kl_kernel<<<(B + WPB - 1) / WPB, WPB * 32, smem_bytes>>>(
        z_pres, z_pres_prob, out, B);
}